// round 8
// baseline (speedup 1.0000x reference)
#include <cuda_runtime.h>
#include <math.h>
#include <stdint.h>

// Problem shapes (fixed by the dataset)
#define Bv   32
#define Sv   4096
#define BSv  (Bv * Sv)      // 131072 rows
#define Dv   768            // K
#define Hv   1024           // N
#define BM   128
#define BN   128
#define BK   32
#define NT   (Hv / BN)      // 8 N-tiles
#define NCH  (Dv / BK)      // 24 k-chunks
#define SKM  136            // smem k-row stride in floats (bank-bijective)
#define TILE (BK * SKM)     // 4352 floats per tile

#define SMEM_FLOATS (8 * TILE + 512 + 256)
#define SMEM_BYTES  (SMEM_FLOATS * 4)      // 142336

// ---------------- scratch (static device globals; no allocation) ----------
__device__ float g_mu[BSv];
__device__ float g_rstd[BSv];
__device__ float g_scores[BSv];
__device__ float g_part[NT * BSv];
__device__ float g_W1s[Hv * Dv];   // tf32-rounded hi part of ln_g-folded W1
__device__ float g_W2s[Hv * Dv];   // tf32-rounded residual
__device__ float g_hbias[Hv];

// ---------------- helpers ---------------------------------------------------
__device__ __forceinline__ uint32_t tf32_rna(float x) {
    uint32_t r;
    asm("cvt.rna.tf32.f32 %0, %1;" : "=r"(r) : "f"(x));
    return r;
}
#define MMA_TF32(c, a, b)                                                    \
    asm volatile("mma.sync.aligned.m16n8k8.row.col.f32.tf32.tf32.f32 "      \
                 "{%0,%1,%2,%3}, {%4,%5,%6,%7}, {%8,%9}, {%0,%1,%2,%3};"    \
                 : "+f"((c)[0]), "+f"((c)[1]), "+f"((c)[2]), "+f"((c)[3])   \
                 : "r"((a)[0]), "r"((a)[1]), "r"((a)[2]), "r"((a)[3]),      \
                   "r"((b)[0]), "r"((b)[1]))

__device__ __forceinline__ float gelu_exact(float x) {
    return 0.5f * x * (1.0f + erff(x * 0.7071067811865475f));
}
__device__ __forceinline__ float softplusf(float x) {
    return fmaxf(x, 0.0f) + log1pf(expf(-fabsf(x)));
}

// ---------------- prep: fold ln_g into W1, split into 2 tf32 parts --------
__global__ void split_w(const float* __restrict__ w1, const float* __restrict__ lng) {
    int i = blockIdx.x * 256 + threadIdx.x;   // i < Hv*Dv
    int d = i % Dv;
    float w = w1[i] * lng[d];
    uint32_t h = tf32_rna(w);
    float hf = __uint_as_float(h);
    uint32_t l = tf32_rna(w - hf);
    g_W1s[i] = hf;
    g_W2s[i] = __uint_as_float(l);
}

__global__ void prep_hbias(const float* __restrict__ w1, const float* __restrict__ lnb,
                           const float* __restrict__ b1) {
    int h    = blockIdx.x * 8 + (threadIdx.x >> 5);
    int lane = threadIdx.x & 31;
    const float* wr = w1 + (size_t)h * Dv;
    float s = 0.0f;
    for (int d = lane; d < Dv; d += 32) s = fmaf(lnb[d], wr[d], s);
#pragma unroll
    for (int o = 16; o; o >>= 1) s += __shfl_xor_sync(0xffffffffu, s, o);
    if (lane == 0) g_hbias[h] = s + b1[h];
}

// ---------------- LayerNorm stats: one warp per row -----------------------
__global__ void ln_stats(const float* __restrict__ emb, const float* __restrict__ attn) {
    int row  = blockIdx.x * 8 + (threadIdx.x >> 5);
    int lane = threadIdx.x & 31;
    const float4* ev = (const float4*)(emb + (size_t)row * Dv);
    float at = attn[row];
    float s = 0.0f, ss = 0.0f;
#pragma unroll
    for (int j = 0; j < Dv / 128; j++) {
        float4 v = ev[lane + 32 * j];
        float a = v.x * at, b = v.y * at, c = v.z * at, d = v.w * at;
        s += a + b + c + d;
        ss = fmaf(a, a, ss); ss = fmaf(b, b, ss);
        ss = fmaf(c, c, ss); ss = fmaf(d, d, ss);
    }
#pragma unroll
    for (int o = 16; o; o >>= 1) {
        s  += __shfl_xor_sync(0xffffffffu, s,  o);
        ss += __shfl_xor_sync(0xffffffffu, ss, o);
    }
    if (lane == 0) {
        float mu  = s * (1.0f / Dv);
        float var = fmaxf(ss * (1.0f / Dv) - mu * mu, 0.0f);
        g_mu[row]   = mu;
        g_rstd[row] = 1.0f / sqrtf(var + 1e-5f);
    }
}

// ---------------- fused LN + 3xTF32 GEMM + GELU + w2-dot ------------------
// 128x128x32 tiles, 256 threads (8 warps, 2x4), warp tile 64x32,
// mma.sync m16n8k8 tf32, products A1B1 + A1B2 + A2B1.
// Smem tiles stored [k][m] / [k][n] with stride SKM=136 -> conflict-free.

__global__ void __launch_bounds__(256, 1)
gemm_tf32(const float* __restrict__ emb, const float* __restrict__ attn,
          const float* __restrict__ w2) {
    extern __shared__ float smf[];
    float* red  = smf + 8 * TILE;     // [128][4]
    float* srow = red + 512;          // [128]
    float* trow = srow + 128;         // [128]

    int nt = blockIdx.x, mt = blockIdx.y;
    int m0 = mt * BM, n0 = nt * BN;
    int tid = threadIdx.x;
    int lane = tid & 31, wid = tid >> 5;
    int warp_m = wid >> 2, warp_n = wid & 3;  // 2 x 4
    int g = lane >> 2, tig = lane & 3;

    if (tid < BM) {
        int m = m0 + tid;
        float rs = g_rstd[m];
        srow[tid] = attn[m] * rs;
        trow[tid] = g_mu[m] * rs;
    }
    __syncthreads();

    // global-load mapping: lm = row (A) / col-row (B), quads qb..qb+3 of k
    int lm = tid & 127;
    int qb = (tid >> 7) * 4;          // float4-quad start within 32-k chunk
    const float4* ea  = (const float4*)(emb   + (size_t)(m0 + lm) * Dv) + qb;
    const float4* eb1 = (const float4*)(g_W1s + (size_t)(n0 + lm) * Dv) + qb;
    const float4* eb2 = (const float4*)(g_W2s + (size_t)(n0 + lm) * Dv) + qb;
    float sA = srow[lm], tA = trow[lm];

    float acc[4][4][4];
#pragma unroll
    for (int tm = 0; tm < 4; tm++)
#pragma unroll
        for (int tn = 0; tn < 4; tn++)
#pragma unroll
            for (int e = 0; e < 4; e++) acc[tm][tn][e] = 0.0f;

    float4 pa[4], pb1[4], pb2[4];
#define PREFETCH(C)                                                \
    do {                                                           \
        _Pragma("unroll")                                          \
        for (int i = 0; i < 4; i++) {                              \
            pa[i]  = ea[(C) * 8 + i];                              \
            pb1[i] = eb1[(C) * 8 + i];                             \
            pb2[i] = eb2[(C) * 8 + i];                             \
        }                                                          \
    } while (0)

#define STORE_BUF(ST)                                                        \
    do {                                                                     \
        float* A1 = smf + ((ST) * 4 + 0) * TILE;                             \
        float* A2 = smf + ((ST) * 4 + 1) * TILE;                             \
        float* B1 = smf + ((ST) * 4 + 2) * TILE;                             \
        float* B2 = smf + ((ST) * 4 + 3) * TILE;                             \
        _Pragma("unroll")                                                    \
        for (int i = 0; i < 4; i++) {                                        \
            int kq = (qb + i) * 4;                                           \
            float xs[4] = {pa[i].x, pa[i].y, pa[i].z, pa[i].w};              \
            float bh[4] = {pb1[i].x, pb1[i].y, pb1[i].z, pb1[i].w};          \
            float bl[4] = {pb2[i].x, pb2[i].y, pb2[i].z, pb2[i].w};          \
            _Pragma("unroll")                                                \
            for (int j = 0; j < 4; j++) {                                    \
                float x = fmaf(xs[j], sA, -tA);                              \
                uint32_t x1 = tf32_rna(x);                                   \
                float x1f = __uint_as_float(x1);                             \
                uint32_t x2 = tf32_rna(x - x1f);                             \
                A1[(kq + j) * SKM + lm] = x1f;                               \
                A2[(kq + j) * SKM + lm] = __uint_as_float(x2);               \
                B1[(kq + j) * SKM + lm] = bh[j];                             \
                B2[(kq + j) * SKM + lm] = bl[j];                             \
            }                                                                \
        }                                                                    \
    } while (0)

    PREFETCH(0);
    STORE_BUF(0);
    __syncthreads();

    int st = 0;
#pragma unroll 1
    for (int c = 0; c < NCH; c++) {
        if (c + 1 < NCH) PREFETCH(c + 1);

        const float* A1 = smf + (st * 4 + 0) * TILE;
        const float* A2 = smf + (st * 4 + 1) * TILE;
        const float* B1 = smf + (st * 4 + 2) * TILE;
        const float* B2 = smf + (st * 4 + 3) * TILE;
#pragma unroll
        for (int ks = 0; ks < 4; ks++) {
            int kb = ks * 8;
            uint32_t a1[4][4], a2[4][4], b1[4][2], b2[4][2];
#pragma unroll
            for (int tm = 0; tm < 4; tm++) {
                int row = warp_m * 64 + tm * 16 + g;
                int i00 = (kb + tig) * SKM + row;
                int i01 = (kb + tig + 4) * SKM + row;
                a1[tm][0] = __float_as_uint(A1[i00]);
                a1[tm][1] = __float_as_uint(A1[i00 + 8]);
                a1[tm][2] = __float_as_uint(A1[i01]);
                a1[tm][3] = __float_as_uint(A1[i01 + 8]);
                a2[tm][0] = __float_as_uint(A2[i00]);
                a2[tm][1] = __float_as_uint(A2[i00 + 8]);
                a2[tm][2] = __float_as_uint(A2[i01]);
                a2[tm][3] = __float_as_uint(A2[i01 + 8]);
            }
#pragma unroll
            for (int tn = 0; tn < 4; tn++) {
                int col = warp_n * 32 + tn * 8 + g;
                b1[tn][0] = __float_as_uint(B1[(kb + tig) * SKM + col]);
                b1[tn][1] = __float_as_uint(B1[(kb + tig + 4) * SKM + col]);
                b2[tn][0] = __float_as_uint(B2[(kb + tig) * SKM + col]);
                b2[tn][1] = __float_as_uint(B2[(kb + tig + 4) * SKM + col]);
            }
#pragma unroll
            for (int tm = 0; tm < 4; tm++)
#pragma unroll
                for (int tn = 0; tn < 4; tn++) {
                    MMA_TF32(acc[tm][tn], a1[tm], b1[tn]);
                    MMA_TF32(acc[tm][tn], a1[tm], b2[tn]);
                    MMA_TF32(acc[tm][tn], a2[tm], b1[tn]);
                }
        }

        if (c + 1 < NCH) {
            STORE_BUF(st ^ 1);
            __syncthreads();
            st ^= 1;
        }
    }

    // ---------------- epilogue: gelu(c + hbias) * w2, reduce ---------------
    // thread cols: n0 + warp_n*32 + tn*8 + 2*tig + {0,1}
    float hb[8], ww[8];
#pragma unroll
    for (int tn = 0; tn < 4; tn++)
#pragma unroll
        for (int e = 0; e < 2; e++) {
            int n = n0 + warp_n * 32 + tn * 8 + 2 * tig + e;
            hb[tn * 2 + e] = g_hbias[n];
            ww[tn * 2 + e] = w2[n];
        }

    float rsum[4][2];
#pragma unroll
    for (int tm = 0; tm < 4; tm++) { rsum[tm][0] = 0.0f; rsum[tm][1] = 0.0f; }
#pragma unroll
    for (int tm = 0; tm < 4; tm++)
#pragma unroll
        for (int tn = 0; tn < 4; tn++) {
            rsum[tm][0] += gelu_exact(acc[tm][tn][0] + hb[tn * 2]) * ww[tn * 2]
                         + gelu_exact(acc[tm][tn][1] + hb[tn * 2 + 1]) * ww[tn * 2 + 1];
            rsum[tm][1] += gelu_exact(acc[tm][tn][2] + hb[tn * 2]) * ww[tn * 2]
                         + gelu_exact(acc[tm][tn][3] + hb[tn * 2 + 1]) * ww[tn * 2 + 1];
        }
    // reduce over tig lanes (xor 1, 2)
#pragma unroll
    for (int tm = 0; tm < 4; tm++)
#pragma unroll
        for (int hf = 0; hf < 2; hf++) {
            float v = rsum[tm][hf];
            v += __shfl_xor_sync(0xffffffffu, v, 1);
            v += __shfl_xor_sync(0xffffffffu, v, 2);
            rsum[tm][hf] = v;
        }
    if (tig == 0) {
#pragma unroll
        for (int tm = 0; tm < 4; tm++)
#pragma unroll
            for (int hf = 0; hf < 2; hf++) {
                int row = warp_m * 64 + tm * 16 + hf * 8 + g;
                red[row * 4 + warp_n] = rsum[tm][hf];
            }
    }
    __syncthreads();
    if (tid < BM) {
        float p = red[tid * 4] + red[tid * 4 + 1] + red[tid * 4 + 2] + red[tid * 4 + 3];
        g_part[nt * BSv + m0 + tid] = p;
    }
}

// ---------------- fixed-order partial reduction (deterministic) -----------
__global__ void score_reduce() {
    int i = blockIdx.x * 256 + threadIdx.x;
    float s = 0.0f;
#pragma unroll
    for (int nt = 0; nt < NT; nt++) s += g_part[nt * BSv + i];
    g_scores[i] = s;
}

// ---------------- entmax-1.5 over S via bisection on tau ------------------
__global__ void __launch_bounds__(1024)
entmax_kernel(const float* __restrict__ attn, const float* __restrict__ b2,
              float* __restrict__ zout) {
    __shared__ float sx[Sv];
    __shared__ float red[33];
    int b = blockIdx.x, tid = threadIdx.x;
    int lane = tid & 31, wid = tid >> 5;
    float b2v = b2[0];
    const float* sc = g_scores + (size_t)b * Sv;
    const float* at = attn + (size_t)b * Sv;

    float loc[4], am[4];
    float mx = -3.4e38f;
#pragma unroll
    for (int j = 0; j < 4; j++) {
        int i = tid + j * 1024;
        float a = at[i]; am[j] = a;
        float v = (a == 0.0f) ? -1e9f : sc[i] + b2v;
        v *= 0.5f;
        loc[j] = v;
        mx = fmaxf(mx, v);
    }
#pragma unroll
    for (int o = 16; o; o >>= 1) mx = fmaxf(mx, __shfl_xor_sync(0xffffffffu, mx, o));
    if (lane == 0) red[wid] = mx;
    __syncthreads();
    if (wid == 0) {
        float m = red[lane];
#pragma unroll
        for (int o = 16; o; o >>= 1) m = fmaxf(m, __shfl_xor_sync(0xffffffffu, m, o));
        if (lane == 0) red[32] = m;
    }
    __syncthreads();
    float xmax = red[32];
#pragma unroll
    for (int j = 0; j < 4; j++) sx[tid + j * 1024] = loc[j] - xmax;
    __syncthreads();

    float lo = -1.0f, hi = 0.0f;
    for (int it = 0; it < 30; it++) {
        float mid = 0.5f * (lo + hi);
        float s = 0.0f;
#pragma unroll
        for (int j = 0; j < 4; j++) {
            float d = fmaxf(sx[tid + j * 1024] - mid, 0.0f);
            s = fmaf(d, d, s);
        }
#pragma unroll
        for (int o = 16; o; o >>= 1) s += __shfl_xor_sync(0xffffffffu, s, o);
        __syncthreads();
        if (lane == 0) red[wid] = s;
        __syncthreads();
        if (wid == 0) {
            float t = red[lane];
#pragma unroll
            for (int o = 16; o; o >>= 1) t += __shfl_xor_sync(0xffffffffu, t, o);
            if (lane == 0) red[32] = t;
        }
        __syncthreads();
        float tot = red[32];
        if (tot >= 1.0f) lo = mid; else hi = mid;
    }
    float tau = 0.5f * (lo + hi);
#pragma unroll
    for (int j = 0; j < 4; j++) {
        int i = tid + j * 1024;
        float d = fmaxf(sx[i] - tau, 0.0f);
        zout[(size_t)b * Sv + i] = d * d * am[j];
    }
}

// ---------------- Kumaraswamy gate (g == h numerically) -------------------
__global__ void final_kernel(const float* __restrict__ attn, const float* __restrict__ u,
                             const float* __restrict__ b2, float* __restrict__ out,
                             int out_size) {
    int i = blockIdx.x * 256 + threadIdx.x;
    float a_ = attn[i];
    float sc = (a_ == 0.0f) ? -1e9f : g_scores[i] + b2[0];
    float z = out[i];
    float eff = sc + 2.0f * (2.0f * z - 1.0f);
    float aa = softplusf(eff) + 1e-6f;
    float bbk = softplusf(-eff) + 1e-6f;
    float uc = fminf(fmaxf(u[i], 1e-6f), 1.0f - 1e-6f);
    float xk = powf(1.0f - powf(1.0f - uc, 1.0f / bbk), 1.0f / aa);
    float y = -0.1f + 1.2f * xk;
    float h = (fminf(fmaxf(y, 0.0f), 1.0f) > 0.5f) ? 1.0f : 0.0f;
    out[BSv + i] = h * a_;
    if (i == 0 && out_size >= 2 * BSv + 1) out[2 * BSv] = 0.0f;
}

// ---------------- launch ---------------------------------------------------
extern "C" void kernel_launch(void* const* d_in, const int* in_sizes, int n_in,
                              void* d_out, int out_size) {
    (void)in_sizes; (void)n_in;
    const float* emb  = (const float*)d_in[0];
    const float* attn = (const float*)d_in[1];
    const float* u    = (const float*)d_in[2];
    const float* lng  = (const float*)d_in[3];
    const float* lnb  = (const float*)d_in[4];
    const float* w1   = (const float*)d_in[5];
    const float* b1   = (const float*)d_in[6];
    const float* w2   = (const float*)d_in[7];
    const float* b2   = (const float*)d_in[8];
    float* out = (float*)d_out;

    cudaFuncSetAttribute(gemm_tf32, cudaFuncAttributeMaxDynamicSharedMemorySize,
                         SMEM_BYTES);

    split_w<<<(Hv * Dv) / 256, 256>>>(w1, lng);
    prep_hbias<<<Hv / 8, 256>>>(w1, lnb, b1);
    ln_stats<<<BSv / 8, 256>>>(emb, attn);
    gemm_tf32<<<dim3(NT, BSv / BM), 256, SMEM_BYTES>>>(emb, attn, w2);
    score_reduce<<<BSv / 256, 256>>>();
    entmax_kernel<<<Bv, 1024>>>(attn, b2, out);
    final_kernel<<<BSv / 256, 256>>>(attn, u, b2, out, out_size);
}